// round 4
// baseline (speedup 1.0000x reference)
#include <cuda_runtime.h>
#include <math.h>

#define NLAYER 5
#define HID    128
#define BAT    32
#define TIN    512
#define TTOT   514     // 512 given + 2 autoregressive continuation steps
#define NB0    16      // blocks for layer 0
#define NBL    32      // blocks for layers 1..4
#define HEAD_BID 144
#define GRID_N 145
#define NTHR   256
#define SMEM_BYTES 53504

// persistent device state (allocation-free scratch)
__device__ float g_h[NLAYER][TTOT][HID][BAT];   // hidden states, [k][b]
__device__ float g_xpred[2][BAT];               // predicted inputs for t=512,513
__device__ int   g_done[NLAYER][NBL];           // per-block completed-step counters
__device__ int   g_xdone[2];

__global__ void zero_flags_kernel() {
    int i = blockIdx.x * blockDim.x + threadIdx.x;
    if (i < NLAYER * NBL) ((int*)g_done)[i] = 0;
    if (i < 2) g_xdone[i] = 0;
}

__device__ __forceinline__ float2 ffma2(float w, float2 h, float2 acc) {
    union { float2 f; unsigned long long u; } A, B, C, D;
    A.f = make_float2(w, w); B.f = h; C.f = acc;
    asm("fma.rn.f32x2 %0, %1, %2, %3;" : "=l"(D.u) : "l"(A.u), "l"(B.u), "l"(C.u));
    return D.f;
}

__device__ __forceinline__ float sigm(float v) { return 1.0f / (1.0f + expf(-v)); }

__global__ void __launch_bounds__(NTHR, 1) lstm_main(
    const float* __restrict__ x,    const float* __restrict__ Wih0,
    const float* __restrict__ Wihr, const float* __restrict__ Whh,
    const float* __restrict__ bih,  const float* __restrict__ bhh,
    const float* __restrict__ W1,   const float* __restrict__ b1,
    const float* __restrict__ W2,   const float* __restrict__ b2,
    float* __restrict__ out)
{
    extern __shared__ float smem[];
    float*  sW  = smem;                          // 4096 floats (16KB)
    float2* sH  = (float2*)(smem + 4096);        // 4096 float2 (32KB)
    float2* sG  = (float2*)(smem + 4096 + 8192); // 512 float2 (4KB)
    float*  sB  = smem + 4096 + 8192 + 1024;     // 32
    float*  sWx = sB + 32;                       // 32

    const int tid  = threadIdx.x;
    const int bid  = blockIdx.x;
    const int lane = tid & 31;

    // ================= HEAD BLOCK =================
    if (bid == HEAD_BID) {
        float* zsm  = smem;          // 32 x 129
        float* z2sm = smem + 4224;   // 32 x 129
        for (int m = 0; m < 3; m++) {
            int t = 511 + m;
            if (tid < 32) {
                volatile int* p = &g_done[4][lane];
                while (!__all_sync(0xffffffffu, *p >= t + 1)) {}
                __threadfence();  // acquire
            }
            __syncthreads();
            // z = relu(h4[t]), transpose [k][b] -> zsm[b][k]
            for (int i = tid; i < HID * BAT; i += NTHR) {
                int k = i >> 5, b = i & 31;
                zsm[b * 129 + k] = fmaxf(g_h[4][t][k][b], 0.0f);
            }
            __syncthreads();
            // z2 = relu(z @ W1 + b1): thread (jgroup, b)
            {
                int jg = tid >> 5, b = tid & 31;
                float acc[16];
                #pragma unroll
                for (int jj = 0; jj < 16; jj++) acc[jj] = b1[jg * 16 + jj];
                for (int k = 0; k < HID; k++) {
                    float zv = zsm[b * 129 + k];
                    const float4* wr = (const float4*)(W1 + k * HID + jg * 16);
                    #pragma unroll
                    for (int q = 0; q < 4; q++) {
                        float4 w = wr[q];
                        acc[q*4+0] += w.x * zv; acc[q*4+1] += w.y * zv;
                        acc[q*4+2] += w.z * zv; acc[q*4+3] += w.w * zv;
                    }
                }
                #pragma unroll
                for (int jj = 0; jj < 16; jj++)
                    z2sm[b * 129 + jg * 16 + jj] = fmaxf(acc[jj], 0.0f);
            }
            __syncthreads();
            // out = z2 @ W2 + b2
            for (int cc = tid; cc < BAT * 16; cc += NTHR) {
                int ob = cc >> 4, oo = cc & 15;
                float s = b2[oo];
                for (int j = 0; j < HID; j++)
                    s += z2sm[ob * 129 + j] * W2[j * 16 + oo];
                if (m == 2) {
                    out[ob * 18 + 2 + oo] = s;
                } else if (oo == 15) {
                    out[ob * 18 + m] = s;
                    g_xpred[m][ob] = s;
                }
            }
            __syncthreads();
            if (m < 2 && tid == 0) {
                __threadfence();  // release
                *(volatile int*)&g_xdone[m] = 1;
            }
        }
        return;
    }

    // ================= LSTM LAYER BLOCKS =================
    int layer, U, u0, NB;
    if (bid < NB0) { layer = 0; U = 8; NB = NB0; u0 = bid * 8; }
    else {
        layer = 1 + (bid - NB0) / NBL;
        U = 4; NB = NBL; u0 = ((bid - NB0) % NBL) * 4;
    }
    const int NBbelow = (layer == 1) ? NB0 : NBL;
    const int myblk   = (layer == 0) ? bid : (bid - NB0) % NBL;

    // stage weights into SMEM (once)
    if (layer == 0) {
        for (int i = tid; i < 32 * 128; i += NTHR) {
            int r = i >> 7, k = i & 127;
            int R = (r >> 3) * HID + u0 + (r & 7);
            sW[r * 128 + k] = Whh[R * HID + k];
        }
        if (tid < 32) {
            int R = (tid >> 3) * HID + u0 + (tid & 7);
            sWx[tid] = Wih0[R];
            sB[tid]  = bih[R] + bhh[R];
        }
    } else {
        const float* wih = Wihr + (size_t)(layer - 1) * 512 * HID;
        const float* whh = Whh  + (size_t)layer * 512 * HID;
        for (int i = tid; i < 16 * 256; i += NTHR) {
            int r = i >> 8, k = i & 255;
            int R = (r >> 2) * HID + u0 + (r & 3);
            sW[r * 256 + k] = (k < 128) ? wih[R * HID + k] : whh[R * HID + (k - 128)];
        }
        if (tid < 16) {
            int R = (tid >> 2) * HID + u0 + (tid & 3);
            sB[tid] = bih[layer * 512 + R] + bhh[layer * 512 + R];
        }
    }
    __syncthreads();

    const int bp = tid & 15;            // batch pair index
    int r0, r1 = -1;
    if (layer == 0) {                   // two gate rows per thread
        int g0 = tid >> 7;
        int uu = (tid >> 4) & 7;
        r0 = g0 * 8 + uu;
        r1 = (g0 + 2) * 8 + uu;
    } else {
        int g  = tid >> 6;
        int uu = (tid >> 4) & 3;
        r0 = g * 4 + uu;
    }
    const bool isact = (layer == 0) ? (tid < 128) : (tid < 64);
    const int  au    = (layer == 0) ? ((tid >> 4) & 7) : ((tid >> 4) & 3);
    float2 cst = make_float2(0.0f, 0.0f);

    for (int t = 0; t < TTOT; t++) {
        // ---- parallel flag poll (warp 0) ----
        if (tid < 32) {
            volatile int* pown = &g_done[layer][lane];
            bool needOwn = (lane < NB) && (t > 0);
            bool ok;
            if (layer > 0) {
                volatile int* pbel = &g_done[layer - 1][lane];
                bool needBel = lane < NBbelow;
                do {
                    ok = (!needOwn || *pown >= t) && (!needBel || *pbel >= t + 1);
                } while (!__all_sync(0xffffffffu, ok));
            } else {
                bool needX = (lane == 0) && (t >= TIN);
                volatile int* px = needX ? &g_xdone[t - TIN] : &g_xdone[0];
                do {
                    ok = (!needOwn || *pown >= t) && (!needX || *px >= 1);
                } while (!__all_sync(0xffffffffu, ok));
            }
            __threadfence();  // acquire
        }
        __syncthreads();

        // ---- merged staging: below-h (k 0..127) then prev-h (k 128..255) ----
        {
            float4* dst = (float4*)sH;
            if (layer > 0) {
                const float4* srcB = (const float4*)&g_h[layer - 1][t][0][0];
                #pragma unroll
                for (int i = 0; i < 4; i++) dst[tid + i * 256] = srcB[tid + i * 256];
                if (t > 0) {
                    const float4* srcP = (const float4*)&g_h[layer][t - 1][0][0];
                    #pragma unroll
                    for (int i = 0; i < 4; i++) dst[1024 + tid + i * 256] = srcP[tid + i * 256];
                }
            } else if (t > 0) {
                const float4* srcP = (const float4*)&g_h[layer][t - 1][0][0];
                #pragma unroll
                for (int i = 0; i < 4; i++) dst[tid + i * 256] = srcP[tid + i * 256];
            }
        }
        __syncthreads();

        float2 a0 = make_float2(sB[r0], sB[r0]);
        float2 a1 = (layer == 0) ? make_float2(sB[r1], sB[r1]) : make_float2(0.f, 0.f);

        if (layer > 0) {
            const float4* w4 = (const float4*)(sW + r0 * 256);
            int n4 = (t > 0) ? 64 : 32;
            #pragma unroll 4
            for (int k4 = 0; k4 < n4; k4++) {
                float4 wv = w4[k4];
                const float2* hp = sH + k4 * 64 + bp;
                a0 = ffma2(wv.x, hp[0],  a0);
                a0 = ffma2(wv.y, hp[16], a0);
                a0 = ffma2(wv.z, hp[32], a0);
                a0 = ffma2(wv.w, hp[48], a0);
            }
        } else {
            if (t > 0) {
                const float4* w40 = (const float4*)(sW + r0 * 128);
                const float4* w41 = (const float4*)(sW + r1 * 128);
                #pragma unroll 4
                for (int k4 = 0; k4 < 32; k4++) {
                    float4 wa = w40[k4], wb = w41[k4];
                    const float2* hp = sH + k4 * 64 + bp;
                    float2 h0 = hp[0], h1 = hp[16], h2 = hp[32], h3 = hp[48];
                    a0 = ffma2(wa.x, h0, a0); a1 = ffma2(wb.x, h0, a1);
                    a0 = ffma2(wa.y, h1, a0); a1 = ffma2(wb.y, h1, a1);
                    a0 = ffma2(wa.z, h2, a0); a1 = ffma2(wb.z, h2, a1);
                    a0 = ffma2(wa.w, h3, a0); a1 = ffma2(wb.w, h3, a1);
                }
            }
            float2 xv;
            if (t < TIN)
                xv = make_float2(x[(2 * bp) * TIN + t], x[(2 * bp + 1) * TIN + t]);
            else
                xv = make_float2(g_xpred[t - TIN][2 * bp], g_xpred[t - TIN][2 * bp + 1]);
            a0 = ffma2(sWx[r0], xv, a0);
            a1 = ffma2(sWx[r1], xv, a1);
        }

        // ---- exchange gates, activate, publish h ----
        sG[r0 * 16 + bp] = a0;
        if (layer == 0) sG[r1 * 16 + bp] = a1;
        __syncthreads();

        if (isact) {
            float2 gi = sG[(0 * U + au) * 16 + bp];
            float2 gf = sG[(1 * U + au) * 16 + bp];
            float2 gg = sG[(2 * U + au) * 16 + bp];
            float2 go = sG[(3 * U + au) * 16 + bp];
            float2 hout;
            {
                float iv = sigm(gi.x), fv = sigm(gf.x);
                float gv = tanhf(gg.x), ov = sigm(go.x);
                cst.x = fv * cst.x + iv * gv;
                hout.x = ov * tanhf(cst.x);
            }
            {
                float iv = sigm(gi.y), fv = sigm(gf.y);
                float gv = tanhf(gg.y), ov = sigm(go.y);
                cst.y = fv * cst.y + iv * gv;
                hout.y = ov * tanhf(cst.y);
            }
            *(float2*)&g_h[layer][t][u0 + au][2 * bp] = hout;
        }
        __syncthreads();
        if (tid == 0) {
            __threadfence();  // release: h stores (ordered via bar.sync) before flag
            *(volatile int*)&g_done[layer][myblk] = t + 1;
        }
    }
}

extern "C" void kernel_launch(void* const* d_in, const int* in_sizes, int n_in,
                              void* d_out, int out_size) {
    const float* x    = (const float*)d_in[0];
    // d_in[1] = future (fixed 18)
    const float* Wih0 = (const float*)d_in[2];
    const float* Wihr = (const float*)d_in[3];
    const float* Whh  = (const float*)d_in[4];
    const float* bih  = (const float*)d_in[5];
    const float* bhh  = (const float*)d_in[6];
    const float* W1   = (const float*)d_in[7];
    const float* b1   = (const float*)d_in[8];
    const float* W2   = (const float*)d_in[9];
    const float* b2   = (const float*)d_in[10];
    float* out = (float*)d_out;

    static bool attr_set = false;
    if (!attr_set) {
        cudaFuncSetAttribute(lstm_main, cudaFuncAttributeMaxDynamicSharedMemorySize,
                             SMEM_BYTES);
        attr_set = true;
    }

    zero_flags_kernel<<<1, 256>>>();
    lstm_main<<<GRID_N, NTHR, SMEM_BYTES>>>(x, Wih0, Wihr, Whh, bih, bhh,
                                            W1, b1, W2, b2, out);
}